// round 11
// baseline (speedup 1.0000x reference)
#include <cuda_runtime.h>
#include <math.h>

// StatefulSynapseNet, R11: R10 structure (dual-sample warp, const-port
// weights, f32x2 FFMA GEMMs in two o-halves, h2 overlay, set.ge scans)
// with the y buffer re-laid as pitch-32 XOR-swizzled (addr = t*32 + (o^t))
// to shrink smem to 28,672B/block, and __launch_bounds__(128,8) to force a
// 64-reg target -> 8 blocks/SM (occ 41% -> ~47%).

typedef unsigned long long ull;

__device__ __forceinline__ ull pack2(float lo, float hi) {
    ull r; asm("mov.b64 %0, {%1,%2};" : "=l"(r) : "f"(lo), "f"(hi)); return r;
}
__device__ __forceinline__ void unpack2(ull v, float& lo, float& hi) {
    asm("mov.b64 {%0,%1}, %2;" : "=f"(lo), "=f"(hi) : "l"(v));
}
__device__ __forceinline__ ull ffma2(ull a, ull b, ull c) {
    ull d; asm("fma.rn.f32x2 %0, %1, %2, %3;" : "=l"(d) : "l"(a), "l"(b), "l"(c)); return d;
}
__device__ __forceinline__ float set_ge(float a, float b) {
    float d; asm("set.ge.f32.f32 %0, %1, %2;" : "=f"(d) : "f"(a), "f"(b)); return d;
}

#define T_DIM 28
#define F_DIM 28
#define C1 32
#define C2 10
#define WARPS 4
#define SPW 2
#define YP 32              // y pitch 32, XOR-swizzled: addr = t*32 + (o^t)
#define H2P 29
#define REGION 896         // 28*32 floats per sample (h2's 290 floats overlay)

// constant-block layout (floats) — identical to R6/R8/R10
#define OFF_W1T 0          // [f*32 + o] = W1[o*28+f]
#define OFF_W2  896        // [j*32 + o]
#define OFF_B1  1216
#define OFF_B2  1248
#define OFF_ITAU 1258
#define CP_SIZE 1280

__constant__ __align__(16) float c_P[CP_SIZE];
__device__   __align__(16) float g_stage[CP_SIZE];

__global__ void setup_kernel(const float* __restrict__ W1,
                             const float* __restrict__ b1,
                             const float* __restrict__ w_syn,
                             const float* __restrict__ W2,
                             const float* __restrict__ b2)
{
    int i = threadIdx.x;
    for (int idx = i; idx < C1 * F_DIM; idx += 1024) {
        int f = idx >> 5, o = idx & 31;
        g_stage[OFF_W1T + idx] = W1[o * F_DIM + f];
    }
    for (int idx = i; idx < C2 * C1; idx += 1024)
        g_stage[OFF_W2 + idx] = W2[idx];
    if (i < C1) g_stage[OFF_B1 + i] = b1[i];
    if (i < C2) g_stage[OFF_B2 + i] = b2[i];
    if (i == 0) g_stage[OFF_ITAU] = 1.0f / (1.0f + expf(-w_syn[0]));
}

__global__ __launch_bounds__(WARPS * 32, 8)
void snn_kernel(const float* __restrict__ x, float* __restrict__ out, int N)
{
    __shared__ float sh[WARPS * SPW * REGION];
    const int lane = threadIdx.x & 31;
    const int warp = threadIdx.x >> 5;
    const int n0 = (blockIdx.x * WARPS + warp) * SPW;
    if (n0 >= N) return;
    const bool has_b = (n0 + 1 < N);
    const int n1 = has_b ? (n0 + 1) : n0;

    float* shA = sh + warp * (SPW * REGION);   // y [t][o] swizzled; h2 overlays
    float* shB = shA + REGION;
    const bool tl = (lane < T_DIM);
    const int t_eff = tl ? lane : (T_DIM - 1);

    const float* xa = x + (size_t)n0 * (F_DIM * T_DIM) + t_eff;
    const float* xb = x + (size_t)n1 * (F_DIM * T_DIM) + t_eff;

    // ---- phase 1: lane = t, two o-halves; acc = 8 ull per sample per half ----
#pragma unroll
    for (int half = 0; half < 2; ++half) {
        ull accA[8], accB[8];
#pragma unroll
        for (int p = 0; p < 8; ++p) {
            ull b = *reinterpret_cast<const ull*>(c_P + OFF_B1 + half * 16 + 2 * p);
            accA[p] = b; accB[p] = b;
        }
#pragma unroll 7
        for (int f = 0; f < F_DIM; ++f) {
            float xva = __ldg(xa + f * T_DIM);       // in-bounds (clamped base)
            float xvb = __ldg(xb + f * T_DIM);
            ull xpa = pack2(xva, xva);
            ull xpb = pack2(xvb, xvb);
            const ulonglong2* wq =
                reinterpret_cast<const ulonglong2*>(c_P + OFF_W1T + f * C1 + half * 16);
#pragma unroll
            for (int q = 0; q < 4; ++q) {            // each const load feeds 4 FFMA2
                ulonglong2 w = wq[q];
                accA[2 * q]     = ffma2(xpa, w.x, accA[2 * q]);
                accB[2 * q]     = ffma2(xpb, w.x, accB[2 * q]);
                accA[2 * q + 1] = ffma2(xpa, w.y, accA[2 * q + 1]);
                accB[2 * q + 1] = ffma2(xpb, w.y, accB[2 * q + 1]);
            }
        }
        if (tl) {                                    // swizzled stores: bank = o^t
            float* ra = shA + lane * YP;
            float* rb = shB + lane * YP;
#pragma unroll
            for (int p = 0; p < 8; ++p) {
                float a0, a1, b0, b1v;
                unpack2(accA[p], a0, a1);
                unpack2(accB[p], b0, b1v);
                int o0 = half * 16 + 2 * p;
                ra[o0 ^ lane]       = a0;
                ra[(o0 + 1) ^ lane] = a1;
                rb[o0 ^ lane]       = b0;
                rb[(o0 + 1) ^ lane] = b1v;
            }
        }
    }
    __syncwarp();

    // ---- IF scan + synapse filter: lane = o; swizzled column access ----
    {
        const float itau = c_P[OFF_ITAU];
        float va = 0.0f, ga = 0.0f, vb = 0.0f, gb = 0.0f;
#pragma unroll
        for (int t = 0; t < T_DIM; ++t) {
            int a = t * YP + (lane ^ t);             // bank = lane^t, permutation
            float ha = shA[a];
            float hb = shB[a];
            va += ha;                             vb += hb;
            float sa = set_ge(va, 1.0f);          float sb = set_ge(vb, 1.0f);
            va = fmaf(va, -sa, va);               vb = fmaf(vb, -sb, vb);
            ga = fmaf(ga, -itau, ga) + sa;        gb = fmaf(gb, -itau, gb) + sb;
            shA[a] = ga;
            shB[a] = gb;
        }
    }
    __syncwarp();

    // ---- phase 2: lane = t, two o-halves, scalar partials; h2 overlays y ----
    {
        float pA[C2], pB[C2];
#pragma unroll
        for (int j = 0; j < C2; ++j) { pA[j] = 0.0f; pB[j] = 0.0f; }

        if (tl) {
            const float* ya = shA + lane * YP;
            const float* yb = shB + lane * YP;
#pragma unroll
            for (int half = 0; half < 2; ++half) {
                ull yqa[8], yqb[8];
#pragma unroll
                for (int q = 0; q < 8; ++q) {
                    int o0 = half * 16 + 2 * q;
                    yqa[q] = pack2(ya[o0 ^ lane], ya[(o0 + 1) ^ lane]);
                    yqb[q] = pack2(yb[o0 ^ lane], yb[(o0 + 1) ^ lane]);
                }
#pragma unroll
                for (int j = 0; j < C2; ++j) {
                    ull a2 = 0ULL, b2a = 0ULL;
                    const ulonglong2* wq2 =
                        reinterpret_cast<const ulonglong2*>(c_P + OFF_W2 + j * C1 + half * 16);
#pragma unroll
                    for (int q = 0; q < 4; ++q) {
                        ulonglong2 w = wq2[q];
                        a2  = ffma2(yqa[2 * q],     w.x, a2);
                        b2a = ffma2(yqb[2 * q],     w.x, b2a);
                        a2  = ffma2(yqa[2 * q + 1], w.y, a2);
                        b2a = ffma2(yqb[2 * q + 1], w.y, b2a);
                    }
                    float u0, u1, v0, v1;
                    unpack2(a2, u0, u1);
                    unpack2(b2a, v0, v1);
                    pA[j] += u0 + u1;
                    pB[j] += v0 + v1;
                }
            }
        }
        __syncwarp();                          // all y reads done -> overlay h2

        if (tl) {
#pragma unroll
            for (int j = 0; j < C2; ++j) {
                float bj = c_P[OFF_B2 + j];
                shA[j * H2P + lane] = pA[j] + bj;   // h2 [j][t] pitch 29
                shB[j * H2P + lane] = pB[j] + bj;
            }
        }
    }
    __syncwarp();

    // ---- second IF scan + mean: 20 lanes (j = lane&15, sample = lane>>4) ----
    {
        int sj = lane & 15;
        int ss = lane >> 4;
        if (sj < C2 && (ss == 0 || has_b)) {
            const float* h2 = ss ? shB : shA;
            float v = 0.0f, cnt = 0.0f;
#pragma unroll
            for (int t = 0; t < T_DIM; ++t) {
                v += h2[sj * H2P + t];
                float s = set_ge(v, 1.0f);
                cnt += s;
                v = fmaf(v, -s, v);
            }
            int nn = ss ? n1 : n0;
            out[(size_t)nn * C2 + sj] = cnt * (1.0f / 28.0f);
        }
    }
}

extern "C" void kernel_launch(void* const* d_in, const int* in_sizes, int n_in,
                              void* d_out, int out_size)
{
    const float* x     = (const float*)d_in[0];
    const float* W1    = (const float*)d_in[1];
    const float* b1    = (const float*)d_in[2];
    const float* w_syn = (const float*)d_in[3];
    const float* W2    = (const float*)d_in[4];
    const float* b2    = (const float*)d_in[5];
    float* out = (float*)d_out;

    const int N = in_sizes[0] / (F_DIM * T_DIM);

    setup_kernel<<<1, 1024>>>(W1, b1, w_syn, W2, b2);

    void* sp = nullptr;
    cudaGetSymbolAddress(&sp, g_stage);
    cudaMemcpyToSymbolAsync(c_P, sp, CP_SIZE * sizeof(float), 0,
                            cudaMemcpyDeviceToDevice, 0);

    const int spb = WARPS * SPW;
    const int blocks = (N + spb - 1) / spb;
    snn_kernel<<<blocks, WARPS * 32>>>(x, out, N);
}

// round 12
// speedup vs baseline: 1.0361x; 1.0361x over previous
#include <cuda_runtime.h>
#include <math.h>

// StatefulSynapseNet, R12: R10 base (dual-sample warp, const-port weights,
// f32x2 FFMA GEMMs in two o-halves, pitch-33 transposes) + LINEARITY TRICK:
// the synapse filter commutes with the W2 GEMM, so scan1 emits only spike
// BITMASKS (ballot -> H-row pad word), phase 2 GEMMs on binary spikes
// reconstructed via ALU bit tricks, and the g/u recurrence moves to the
// final 10-dim scan. Removes ~112 fma-pipe ops + ~130 L1 ops per pair.

typedef unsigned long long ull;

__device__ __forceinline__ ull pack2(float lo, float hi) {
    ull r; asm("mov.b64 %0, {%1,%2};" : "=l"(r) : "f"(lo), "f"(hi)); return r;
}
__device__ __forceinline__ void unpack2(ull v, float& lo, float& hi) {
    asm("mov.b64 {%0,%1}, %2;" : "=f"(lo), "=f"(hi) : "l"(v));
}
__device__ __forceinline__ ull ffma2(ull a, ull b, ull c) {
    ull d; asm("fma.rn.f32x2 %0, %1, %2, %3;" : "=l"(d) : "l"(a), "l"(b), "l"(c)); return d;
}
__device__ __forceinline__ float set_ge(float a, float b) {
    float d; asm("set.ge.f32.f32 %0, %1, %2;" : "=f"(d) : "f"(a), "f"(b)); return d;
}
// spike bit o of mask m -> 1.0f or 0.0f, pure ALU (shift/shift/and)
__device__ __forceinline__ float bitf(unsigned m, int o) {
    return __uint_as_float((unsigned)(((int)(m << (31 - o))) >> 31) & 0x3F800000u);
}

#define T_DIM 28
#define F_DIM 28
#define C1 32
#define C2 10
#define WARPS 4
#define SPW 2
#define HP 33              // H pitch 33: 32 data + 1 pad word (holds spike mask)
#define H2P 29             // z buffer pitch (overlays dead H region)
#define REGION 928         // 28*33 = 924 floats, padded

// constant-block layout (floats) — identical to R6/R8/R10
#define OFF_W1T 0          // [f*32 + o] = W1[o*28+f]
#define OFF_W2  896        // [j*32 + o]
#define OFF_B1  1216
#define OFF_B2  1248
#define OFF_ITAU 1258
#define CP_SIZE 1280

__constant__ __align__(16) float c_P[CP_SIZE];
__device__   __align__(16) float g_stage[CP_SIZE];

__global__ void setup_kernel(const float* __restrict__ W1,
                             const float* __restrict__ b1,
                             const float* __restrict__ w_syn,
                             const float* __restrict__ W2,
                             const float* __restrict__ b2)
{
    int i = threadIdx.x;
    for (int idx = i; idx < C1 * F_DIM; idx += 1024) {
        int f = idx >> 5, o = idx & 31;
        g_stage[OFF_W1T + idx] = W1[o * F_DIM + f];
    }
    for (int idx = i; idx < C2 * C1; idx += 1024)
        g_stage[OFF_W2 + idx] = W2[idx];
    if (i < C1) g_stage[OFF_B1 + i] = b1[i];
    if (i < C2) g_stage[OFF_B2 + i] = b2[i];
    if (i == 0) g_stage[OFF_ITAU] = 1.0f / (1.0f + expf(-w_syn[0]));
}

__global__ __launch_bounds__(WARPS * 32, 7)
void snn_kernel(const float* __restrict__ x, float* __restrict__ out, int N)
{
    __shared__ float sh[WARPS * SPW * REGION];
    const int lane = threadIdx.x & 31;
    const int warp = threadIdx.x >> 5;
    const int n0 = (blockIdx.x * WARPS + warp) * SPW;
    if (n0 >= N) return;
    const bool has_b = (n0 + 1 < N);
    const int n1 = has_b ? (n0 + 1) : n0;

    float* shA = sh + warp * (SPW * REGION);   // H [t][o] pitch 33 (+mask pad)
    float* shB = shA + REGION;
    const bool tl = (lane < T_DIM);
    const int t_eff = tl ? lane : (T_DIM - 1);

    const float* xa = x + (size_t)n0 * (F_DIM * T_DIM) + t_eff;
    const float* xb = x + (size_t)n1 * (F_DIM * T_DIM) + t_eff;

    // ---- phase 1: lane = t, two o-halves (R8/R10-proven const-port GEMM) ----
#pragma unroll
    for (int half = 0; half < 2; ++half) {
        ull accA[8], accB[8];
#pragma unroll
        for (int p = 0; p < 8; ++p) {
            ull b = *reinterpret_cast<const ull*>(c_P + OFF_B1 + half * 16 + 2 * p);
            accA[p] = b; accB[p] = b;
        }
#pragma unroll 7
        for (int f = 0; f < F_DIM; ++f) {
            float xva = __ldg(xa + f * T_DIM);       // in-bounds (clamped base)
            float xvb = __ldg(xb + f * T_DIM);
            ull xpa = pack2(xva, xva);
            ull xpb = pack2(xvb, xvb);
            const ulonglong2* wq =
                reinterpret_cast<const ulonglong2*>(c_P + OFF_W1T + f * C1 + half * 16);
#pragma unroll
            for (int q = 0; q < 4; ++q) {            // each const load feeds 4 FFMA2
                ulonglong2 w = wq[q];
                accA[2 * q]     = ffma2(xpa, w.x, accA[2 * q]);
                accB[2 * q]     = ffma2(xpb, w.x, accB[2 * q]);
                accA[2 * q + 1] = ffma2(xpa, w.y, accA[2 * q + 1]);
                accB[2 * q + 1] = ffma2(xpb, w.y, accB[2 * q + 1]);
            }
        }
        if (tl) {
#pragma unroll
            for (int p = 0; p < 8; ++p) {
                float a0, a1, b0, b1v;
                unpack2(accA[p], a0, a1);
                unpack2(accB[p], b0, b1v);
                shA[lane * HP + half * 16 + 2 * p]     = a0;
                shA[lane * HP + half * 16 + 2 * p + 1] = a1;
                shB[lane * HP + half * 16 + 2 * p]     = b0;
                shB[lane * HP + half * 16 + 2 * p + 1] = b1v;
            }
        }
    }
    __syncwarp();

    // ---- IF scan (lane = o): spike + reset only; masks -> pad word of row t ----
    {
        unsigned* muA = reinterpret_cast<unsigned*>(shA);
        unsigned* muB = reinterpret_cast<unsigned*>(shB);
        const bool l0 = (lane == 0);
        float va = 0.0f, vb = 0.0f;
#pragma unroll
        for (int t = 0; t < T_DIM; ++t) {
            va += shA[t * HP + lane];
            vb += shB[t * HP + lane];
            bool pa = (va >= 1.0f);
            bool pb = (vb >= 1.0f);
            unsigned ma = __ballot_sync(0xffffffffu, pa);
            unsigned mb = __ballot_sync(0xffffffffu, pb);
            va = pa ? 0.0f : va;                     // hard reset
            vb = pb ? 0.0f : vb;
            if (l0) { muA[t * HP + 32] = ma; muB[t * HP + 32] = mb; }
        }
    }
    __syncwarp();

    // ---- phase 2: lane = t; GEMM on binary spikes from the mask ----
    {
        float pA[C2], pB[C2];
#pragma unroll
        for (int j = 0; j < C2; ++j) { pA[j] = 0.0f; pB[j] = 0.0f; }

        if (tl) {
            const unsigned mA = reinterpret_cast<const unsigned*>(shA)[lane * HP + 32];
            const unsigned mB = reinterpret_cast<const unsigned*>(shB)[lane * HP + 32];
#pragma unroll
            for (int half = 0; half < 2; ++half) {
                ull sqa[8], sqb[8];
#pragma unroll
                for (int q = 0; q < 8; ++q) {        // spikes as packed f32x2, pure ALU
                    int o0 = half * 16 + 2 * q;
                    sqa[q] = pack2(bitf(mA, o0), bitf(mA, o0 + 1));
                    sqb[q] = pack2(bitf(mB, o0), bitf(mB, o0 + 1));
                }
#pragma unroll
                for (int j = 0; j < C2; ++j) {
                    ull a2 = 0ULL, b2a = 0ULL;
                    const ulonglong2* wq2 =
                        reinterpret_cast<const ulonglong2*>(c_P + OFF_W2 + j * C1 + half * 16);
#pragma unroll
                    for (int q = 0; q < 4; ++q) {
                        ulonglong2 w = wq2[q];
                        a2  = ffma2(sqa[2 * q],     w.x, a2);
                        b2a = ffma2(sqb[2 * q],     w.x, b2a);
                        a2  = ffma2(sqa[2 * q + 1], w.y, a2);
                        b2a = ffma2(sqb[2 * q + 1], w.y, b2a);
                    }
                    float u0, u1, v0, v1;
                    unpack2(a2, u0, u1);
                    unpack2(b2a, v0, v1);
                    pA[j] += u0 + u1;
                    pB[j] += v0 + v1;
                }
            }
        }
        __syncwarp();                  // masks consumed -> z may overlay H region

        if (tl) {
#pragma unroll
            for (int j = 0; j < C2; ++j) {
                shA[j * H2P + lane] = pA[j];         // z[j][t] (no b2 yet)
                shB[j * H2P + lane] = pB[j];
            }
        }
    }
    __syncwarp();

    // ---- final scan (20 lanes): u recurrence (filter) + IF scan + mean ----
    {
        int sj = lane & 15;
        int ss = lane >> 4;
        if (sj < C2 && (ss == 0 || has_b)) {
            const float* z = ss ? shB : shA;
            const float itau = c_P[OFF_ITAU];
            const float bj = c_P[OFF_B2 + sj];
            float u = 0.0f, v = 0.0f, cnt = 0.0f;
#pragma unroll
            for (int t = 0; t < T_DIM; ++t) {
                u = fmaf(u, -itau, u) + z[sj * H2P + t];   // u = u - u*itau + z
                v += u + bj;                               // h2 = u + b2
                float s = set_ge(v, 1.0f);
                cnt += s;
                v = fmaf(v, -s, v);                        // exact reset
            }
            int nn = ss ? n1 : n0;
            out[(size_t)nn * C2 + sj] = cnt * (1.0f / 28.0f);
        }
    }
}

extern "C" void kernel_launch(void* const* d_in, const int* in_sizes, int n_in,
                              void* d_out, int out_size)
{
    const float* x     = (const float*)d_in[0];
    const float* W1    = (const float*)d_in[1];
    const float* b1    = (const float*)d_in[2];
    const float* w_syn = (const float*)d_in[3];
    const float* W2    = (const float*)d_in[4];
    const float* b2    = (const float*)d_in[5];
    float* out = (float*)d_out;

    const int N = in_sizes[0] / (F_DIM * T_DIM);

    setup_kernel<<<1, 1024>>>(W1, b1, w_syn, W2, b2);

    void* sp = nullptr;
    cudaGetSymbolAddress(&sp, g_stage);
    cudaMemcpyToSymbolAsync(c_P, sp, CP_SIZE * sizeof(float), 0,
                            cudaMemcpyDeviceToDevice, 0);

    const int spb = WARPS * SPW;
    const int blocks = (N + spb - 1) / spb;
    snn_kernel<<<blocks, WARPS * 32>>>(x, out, N);
}

// round 13
// speedup vs baseline: 1.0618x; 1.0248x over previous
#include <cuda_runtime.h>
#include <math.h>

// StatefulSynapseNet, R13: R10 structure exactly (dual-sample warp, const-port
// weights, f32x2 FFMA GEMMs in two o-halves, pitch-33 transposes, h2 overlay)
// + linearity-lite: scan1 emits spike FLOATS only (no g filter, no ballot);
// the synapse recurrence u = u - u*itau + z and the b2 add are folded into
// the 20-lane final scan (filter commutes with the W2 GEMM).

typedef unsigned long long ull;

__device__ __forceinline__ ull pack2(float lo, float hi) {
    ull r; asm("mov.b64 %0, {%1,%2};" : "=l"(r) : "f"(lo), "f"(hi)); return r;
}
__device__ __forceinline__ void unpack2(ull v, float& lo, float& hi) {
    asm("mov.b64 {%0,%1}, %2;" : "=f"(lo), "=f"(hi) : "l"(v));
}
__device__ __forceinline__ ull ffma2(ull a, ull b, ull c) {
    ull d; asm("fma.rn.f32x2 %0, %1, %2, %3;" : "=l"(d) : "l"(a), "l"(b), "l"(c)); return d;
}
__device__ __forceinline__ float set_ge(float a, float b) {
    float d; asm("set.ge.f32.f32 %0, %1, %2;" : "=f"(d) : "f"(a), "f"(b)); return d;
}

#define T_DIM 28
#define F_DIM 28
#define C1 32
#define C2 10
#define WARPS 4
#define SPW 2
#define HP 33              // H/s pitch, conflict-free scalar pattern (proven)
#define H2P 29             // z buffer pitch (overlays dead H region)
#define REGION 928         // 28*33 = 924 floats, padded to 16B multiple

// constant-block layout (floats) — identical to R6/R8/R10
#define OFF_W1T 0          // [f*32 + o] = W1[o*28+f]
#define OFF_W2  896        // [j*32 + o]
#define OFF_B1  1216
#define OFF_B2  1248
#define OFF_ITAU 1258
#define CP_SIZE 1280

__constant__ __align__(16) float c_P[CP_SIZE];
__device__   __align__(16) float g_stage[CP_SIZE];

__global__ void setup_kernel(const float* __restrict__ W1,
                             const float* __restrict__ b1,
                             const float* __restrict__ w_syn,
                             const float* __restrict__ W2,
                             const float* __restrict__ b2)
{
    int i = threadIdx.x;
    for (int idx = i; idx < C1 * F_DIM; idx += 1024) {
        int f = idx >> 5, o = idx & 31;
        g_stage[OFF_W1T + idx] = W1[o * F_DIM + f];
    }
    for (int idx = i; idx < C2 * C1; idx += 1024)
        g_stage[OFF_W2 + idx] = W2[idx];
    if (i < C1) g_stage[OFF_B1 + i] = b1[i];
    if (i < C2) g_stage[OFF_B2 + i] = b2[i];
    if (i == 0) g_stage[OFF_ITAU] = 1.0f / (1.0f + expf(-w_syn[0]));
}

__global__ __launch_bounds__(WARPS * 32, 7)
void snn_kernel(const float* __restrict__ x, float* __restrict__ out, int N)
{
    __shared__ float sh[WARPS * SPW * REGION];
    const int lane = threadIdx.x & 31;
    const int warp = threadIdx.x >> 5;
    const int n0 = (blockIdx.x * WARPS + warp) * SPW;
    if (n0 >= N) return;
    const bool has_b = (n0 + 1 < N);
    const int n1 = has_b ? (n0 + 1) : n0;

    float* shA = sh + warp * (SPW * REGION);   // H/s [t][o] pitch 33; z overlays
    float* shB = shA + REGION;
    const bool tl = (lane < T_DIM);
    const int t_eff = tl ? lane : (T_DIM - 1); // clamp: x loads unconditional

    const float* xa = x + (size_t)n0 * (F_DIM * T_DIM) + t_eff;
    const float* xb = x + (size_t)n1 * (F_DIM * T_DIM) + t_eff;

    // ---- phase 1: lane = t, two o-halves; acc = 8 ull per sample per half ----
#pragma unroll
    for (int half = 0; half < 2; ++half) {
        ull accA[8], accB[8];
#pragma unroll
        for (int p = 0; p < 8; ++p) {
            ull b = *reinterpret_cast<const ull*>(c_P + OFF_B1 + half * 16 + 2 * p);
            accA[p] = b; accB[p] = b;
        }
#pragma unroll 7
        for (int f = 0; f < F_DIM; ++f) {
            float xva = __ldg(xa + f * T_DIM);           // in-bounds (clamped base)
            float xvb = __ldg(xb + f * T_DIM);
            ull xpa = pack2(xva, xva);
            ull xpb = pack2(xvb, xvb);
            const ulonglong2* wq =
                reinterpret_cast<const ulonglong2*>(c_P + OFF_W1T + f * C1 + half * 16);
#pragma unroll
            for (int q = 0; q < 4; ++q) {                // each const load feeds 4 FFMA2
                ulonglong2 w = wq[q];
                accA[2 * q]     = ffma2(xpa, w.x, accA[2 * q]);
                accB[2 * q]     = ffma2(xpb, w.x, accB[2 * q]);
                accA[2 * q + 1] = ffma2(xpa, w.y, accA[2 * q + 1]);
                accB[2 * q + 1] = ffma2(xpb, w.y, accB[2 * q + 1]);
            }
        }
        if (tl) {
#pragma unroll
            for (int p = 0; p < 8; ++p) {
                float a0, a1, b0, b1v;
                unpack2(accA[p], a0, a1);
                unpack2(accB[p], b0, b1v);
                shA[lane * HP + half * 16 + 2 * p]     = a0;
                shA[lane * HP + half * 16 + 2 * p + 1] = a1;
                shB[lane * HP + half * 16 + 2 * p]     = b0;
                shB[lane * HP + half * 16 + 2 * p + 1] = b1v;
            }
        }
    }
    __syncwarp();

    // ---- IF scan (lane = o): spike + reset ONLY; write s floats in place ----
    {
        float va = 0.0f, vb = 0.0f;
#pragma unroll
        for (int t = 0; t < T_DIM; ++t) {
            float ha = shA[t * HP + lane];
            float hb = shB[t * HP + lane];
            va += ha;                             vb += hb;
            float sa = set_ge(va, 1.0f);          float sb = set_ge(vb, 1.0f);
            va = fmaf(va, -sa, va);               vb = fmaf(vb, -sb, vb);   // exact reset
            shA[t * HP + lane] = sa;              // s[t][o] (filter deferred)
            shB[t * HP + lane] = sb;
        }
    }
    __syncwarp();

    // ---- phase 2: lane = t, two o-halves; z[j][t] = sum_o W2[j][o]*s[t][o] ----
    {
        float pA[C2], pB[C2];
#pragma unroll
        for (int j = 0; j < C2; ++j) { pA[j] = 0.0f; pB[j] = 0.0f; }

        if (tl) {
#pragma unroll
            for (int half = 0; half < 2; ++half) {
                ull yqa[8], yqb[8];
                const float* ya = shA + lane * HP + half * 16;
                const float* yb = shB + lane * HP + half * 16;
#pragma unroll
                for (int q = 0; q < 8; ++q) {
                    yqa[q] = pack2(ya[2 * q], ya[2 * q + 1]);
                    yqb[q] = pack2(yb[2 * q], yb[2 * q + 1]);
                }
#pragma unroll
                for (int j = 0; j < C2; ++j) {
                    ull a2 = 0ULL, b2a = 0ULL;
                    const ulonglong2* wq2 =
                        reinterpret_cast<const ulonglong2*>(c_P + OFF_W2 + j * C1 + half * 16);
#pragma unroll
                    for (int q = 0; q < 4; ++q) {
                        ulonglong2 w = wq2[q];
                        a2  = ffma2(yqa[2 * q],     w.x, a2);
                        b2a = ffma2(yqb[2 * q],     w.x, b2a);
                        a2  = ffma2(yqa[2 * q + 1], w.y, a2);
                        b2a = ffma2(yqb[2 * q + 1], w.y, b2a);
                    }
                    float u0, u1, v0, v1;
                    unpack2(a2, u0, u1);
                    unpack2(b2a, v0, v1);
                    pA[j] += u0 + u1;
                    pB[j] += v0 + v1;
                }
            }
        }
        __syncwarp();                          // all s reads done -> overlay z

        if (tl) {
#pragma unroll
            for (int j = 0; j < C2; ++j) {
                shA[j * H2P + lane] = pA[j];   // z[j][t], b2 folded into final scan
                shB[j * H2P + lane] = pB[j];
            }
        }
    }
    __syncwarp();

    // ---- final scan (20 lanes): u recurrence (synapse filter) + IF + mean ----
    {
        int sj = lane & 15;
        int ss = lane >> 4;
        if (sj < C2 && (ss == 0 || has_b)) {
            const float* z = ss ? shB : shA;
            const float itau = c_P[OFF_ITAU];
            const float bj = c_P[OFF_B2 + sj];
            float u = 0.0f, v = 0.0f, cnt = 0.0f;
#pragma unroll
            for (int t = 0; t < T_DIM; ++t) {
                u = fmaf(u, -itau, u) + z[sj * H2P + t];   // u = u - u*itau + z
                v += u + bj;                               // h2 = u + b2
                float s = set_ge(v, 1.0f);
                cnt += s;
                v = fmaf(v, -s, v);                        // exact reset
            }
            int nn = ss ? n1 : n0;
            out[(size_t)nn * C2 + sj] = cnt * (1.0f / 28.0f);
        }
    }
}

extern "C" void kernel_launch(void* const* d_in, const int* in_sizes, int n_in,
                              void* d_out, int out_size)
{
    const float* x     = (const float*)d_in[0];
    const float* W1    = (const float*)d_in[1];
    const float* b1    = (const float*)d_in[2];
    const float* w_syn = (const float*)d_in[3];
    const float* W2    = (const float*)d_in[4];
    const float* b2    = (const float*)d_in[5];
    float* out = (float*)d_out;

    const int N = in_sizes[0] / (F_DIM * T_DIM);

    setup_kernel<<<1, 1024>>>(W1, b1, w_syn, W2, b2);

    void* sp = nullptr;
    cudaGetSymbolAddress(&sp, g_stage);
    cudaMemcpyToSymbolAsync(c_P, sp, CP_SIZE * sizeof(float), 0,
                            cudaMemcpyDeviceToDevice, 0);

    const int spb = WARPS * SPW;
    const int blocks = (N + spb - 1) / spb;
    snn_kernel<<<blocks, WARPS * 32>>>(x, out, N);
}